// round 9
// baseline (speedup 1.0000x reference)
#include <cuda_runtime.h>

#define DTV      0.02f
#define SQRT_DT  0.141421356237309515f
#define SIGMA    0.5f
#define NSTEP    50
#define BATCH    4096
#define PPC      32            // paths per CTA
#define NCTA     (BATCH / PPC) // 128
#define NTHR     768

typedef unsigned long long u64;

// ---- shared-memory layout (float offsets) ----
#define W_IN   0       // [2][64] = 128
#define B_IN   128     // 64
#define W_H    192     // [3][64][64] = 12288
#define B_H    12480   // [3][64] = 192
#define W_OUT  12672   // 64
#define B_OUT  12736   // 1 (+3 pad)
#define NET_SZ 12740
// activation buffers: NON-dup [64 rows][32 paths] floats (128B/row),
// 8 chunks of 16B per row, XOR-swizzled: phys_chunk = c ^ (r & 7)
#define XBUF     2048
#define OFF_X    (2 * NET_SZ)           // 25480 (16B aligned)
#define OFF_DX   (OFF_X   + XBUF)
#define OFF_XN   (OFF_DX  + XBUF)
#define OFF_DXN  (OFF_XN  + XBUF)
#define OFF_QX   (OFF_DXN + XBUF)
#define OFF_QXN  (OFF_QX  + XBUF)
#define OFF_YS   (OFF_QXN + XBUF)
#define OFF_HD2  (OFF_YS  + 32)         // [3 heads][4 quarters][32]
#define SMEM_FLOATS (OFF_HD2 + 384)
#define SMEM_BYTES  (SMEM_FLOATS * 4)   // ~153 KB

__device__ float g_part[NCTA];
__device__ int   g_count = 0;

__device__ __forceinline__ void cpf(float* d, const float* s, int n, int tid) {
    for (int i = tid; i < n; i += NTHR) d[i] = s[i];
}

__device__ __forceinline__ u64 fma2(u64 a, u64 b, u64 c) {
    u64 d;
    asm("fma.rn.f32x2 %0, %1, %2, %3;" : "=l"(d) : "l"(a), "l"(b), "l"(c));
    return d;
}
__device__ __forceinline__ u64 pk(float lo, float hi) {
    u64 r;
    asm("mov.b64 %0, {%1, %2};" : "=l"(r) : "f"(lo), "f"(hi));
    return r;
}
__device__ __forceinline__ void upk(u64 v, float& lo, float& hi) {
    asm("mov.b64 {%0, %1}, %2;" : "=f"(lo), "=f"(hi) : "l"(v));
}

// Fused hidden layer, warp-specialized:
//  warps 0-15 (YD): h + dh for 1 j-row x 4 paths per thread (full K)
//  warps 16-23 (q): q for 2 j-rows x 4 paths per thread (full K)
// Ends with a CTA sync.
__device__ __forceinline__ void fused_layer(
    const float* __restrict__ Wy, const float* __restrict__ by,
    const float* __restrict__ Wq, const float* __restrict__ bq,
    const float* __restrict__ X,  const float* __restrict__ dXb,
    const float* __restrict__ QX,
    float* __restrict__ Xn, float* __restrict__ dXn, float* __restrict__ QXn,
    int wid, int lane)
{
    if (wid < 16) {
        const int j    = wid * 4 + (lane >> 3);
        const int psub = lane & 7;
        const ulonglong2* X2  = (const ulonglong2*)X;
        const ulonglong2* dX2 = (const ulonglong2*)dXb;
        u64 b2 = pk(by[j], by[j]);
        u64 ah0 = b2, ah1 = b2, ad0 = 0ull, ad1 = 0ull;
#pragma unroll 4
        for (int i = 0; i < 64; i++) {
            float w = Wy[i * 64 + j];
            u64 w2 = pk(w, w);
            int cc = psub ^ (i & 7);
            ulonglong2 xv = X2[i * 8 + cc];
            ulonglong2 dv = dX2[i * 8 + cc];
            ah0 = fma2(w2, xv.x, ah0);
            ah1 = fma2(w2, xv.y, ah1);
            ad0 = fma2(w2, dv.x, ad0);
            ad1 = fma2(w2, dv.y, ad1);
        }
        float h[4], d[4], s[4], c[4];
        upk(ah0, h[0], h[1]); upk(ah1, h[2], h[3]);
        upk(ad0, d[0], d[1]); upk(ad1, d[2], d[3]);
#pragma unroll
        for (int p = 0; p < 4; p++) __sincosf(h[p], &s[p], &c[p]);
        int cc = psub ^ (j & 7);
        ((float4*)Xn)[j * 8 + cc]  = make_float4(s[0], s[1], s[2], s[3]);
        ((float4*)dXn)[j * 8 + cc] = make_float4(c[0] * d[0], c[1] * d[1],
                                                 c[2] * d[2], c[3] * d[3]);
    } else {
        const int g    = wid - 16;
        const int j0   = g * 8 + (lane >> 3) * 2;
        const int psub = lane & 7;
        const ulonglong2* QX2 = (const ulonglong2*)QX;
        u64 a00 = pk(bq[j0], bq[j0]),         a01 = a00;
        u64 a10 = pk(bq[j0 + 1], bq[j0 + 1]), a11 = a10;
#pragma unroll 4
        for (int i = 0; i < 64; i++) {
            float2 wq = *(const float2*)&Wq[i * 64 + j0];
            u64 w0 = pk(wq.x, wq.x);
            u64 w1 = pk(wq.y, wq.y);
            int cc = psub ^ (i & 7);
            ulonglong2 qv = QX2[i * 8 + cc];
            a00 = fma2(w0, qv.x, a00);
            a01 = fma2(w0, qv.y, a01);
            a10 = fma2(w1, qv.x, a10);
            a11 = fma2(w1, qv.y, a11);
        }
        float q0[4], q1[4];
        upk(a00, q0[0], q0[1]); upk(a01, q0[2], q0[3]);
        upk(a10, q1[0], q1[1]); upk(a11, q1[2], q1[3]);
#pragma unroll
        for (int p = 0; p < 4; p++) { q0[p] = __sinf(q0[p]); q1[p] = __sinf(q1[p]); }
        int cc0 = psub ^ (j0 & 7);
        int cc1 = psub ^ ((j0 + 1) & 7);
        ((float4*)QXn)[j0 * 8 + cc0]       = make_float4(q0[0], q0[1], q0[2], q0[3]);
        ((float4*)QXn)[(j0 + 1) * 8 + cc1] = make_float4(q1[0], q1[1], q1[2], q1[3]);
    }
    __syncthreads();
}

// Fused full-net eval; ends with HD2 head partials written and CTA synced.
__device__ __forceinline__ void eval_fused(float* sm, float tval,
                                           int wid, int lane, int tid)
{
    const float* netY = sm;
    const float* netQ = sm + NET_SZ;
    float* X   = sm + OFF_X;
    float* dXb = sm + OFF_DX;
    float* Xn  = sm + OFF_XN;
    float* dXn = sm + OFF_DXN;
    float* QX  = sm + OFF_QX;
    float* QXn = sm + OFF_QXN;
    const float* ys = sm + OFF_YS;

    // ---- input layer ----
    if (tid < 512) {
        // X, dX: thread = 1 row x 4 paths
        int r  = tid >> 3;          // 0..63
        int ch = tid & 7;           // path quad
        int p0 = ch * 4;
        float wtY = netY[W_IN + r], wyY = netY[W_IN + 64 + r];
        float tbY = fmaf(tval, wtY, netY[B_IN + r]);
        float s[4], c[4];
#pragma unroll
        for (int p = 0; p < 4; p++)
            __sincosf(fmaf(ys[p0 + p], wyY, tbY), &s[p], &c[p]);
        int cc = ch ^ (r & 7);
        ((float4*)X)[r * 8 + cc]   = make_float4(s[0], s[1], s[2], s[3]);
        ((float4*)dXb)[r * 8 + cc] = make_float4(c[0] * wyY, c[1] * wyY,
                                                 c[2] * wyY, c[3] * wyY);
    } else {
        // QX: thread = 1 row x 8 paths (2 chunks)
        int u  = tid - 512;
        int r  = u >> 2;            // 0..63
        int c0 = (u & 3) * 2;
        float wtQ = netQ[W_IN + r], wyQ = netQ[W_IN + 64 + r];
        float tbQ = fmaf(tval, wtQ, netQ[B_IN + r]);
#pragma unroll
        for (int t = 0; t < 2; t++) {
            int ch = c0 + t;
            int p0 = ch * 4;
            float sq[4];
#pragma unroll
            for (int p = 0; p < 4; p++)
                sq[p] = __sinf(fmaf(ys[p0 + p], wyQ, tbQ));
            int cc = ch ^ (r & 7);
            ((float4*)QX)[r * 8 + cc] = make_float4(sq[0], sq[1], sq[2], sq[3]);
        }
    }
    __syncthreads();

    fused_layer(netY + W_H,        netY + B_H,       netQ + W_H,        netQ + B_H,
                X, dXb, QX, Xn, dXn, QXn, wid, lane);
    fused_layer(netY + W_H + 4096, netY + B_H + 64,  netQ + W_H + 4096, netQ + B_H + 64,
                Xn, dXn, QXn, X, dXb, QX, wid, lane);
    fused_layer(netY + W_H + 8192, netY + B_H + 128, netQ + W_H + 8192, netQ + B_H + 128,
                X, dXb, QX, Xn, dXn, QXn, wid, lane);

    // ---- head partials: 12 warps = 3 heads x 4 i-quarters ----
    if (wid < 12) {
        int head = wid >> 2, quarter = wid & 3;
        const float* src = (head == 0) ? Xn : (head == 1) ? dXn : QXn;
        const float* wv  = (head == 2) ? (netQ + W_OUT) : (netY + W_OUT);
        int p = lane;
        int pch = p >> 2, pin = p & 3;
        int i0 = quarter * 16;
        float a0 = 0.0f, a1 = 0.0f, a2 = 0.0f, a3 = 0.0f;
#pragma unroll
        for (int i = 0; i < 16; i += 4) {
#pragma unroll
            for (int k = 0; k < 4; k++) {
                int ii = i0 + i + k;
                int off = ii * 32 + (pch ^ (ii & 7)) * 4 + pin;
                float v = src[off] * wv[ii];
                if (k == 0) a0 += v; else if (k == 1) a1 += v;
                else if (k == 2) a2 += v; else a3 += v;
            }
        }
        sm[OFF_HD2 + head * 128 + quarter * 32 + p] = (a0 + a1) + (a2 + a3);
    }
    __syncthreads();
}

__global__ __launch_bounds__(NTHR, 1) void fbsnn_main(
    const float* __restrict__ yWin,  const float* __restrict__ yBin,
    const float* __restrict__ yWh,   const float* __restrict__ yBh,
    const float* __restrict__ yWout, const float* __restrict__ yBout,
    const float* __restrict__ qWin,  const float* __restrict__ qBin,
    const float* __restrict__ qWh,   const float* __restrict__ qBh,
    const float* __restrict__ qWout, const float* __restrict__ qBout,
    const float* __restrict__ y0,    const float* __restrict__ dW,
    float* __restrict__ out)
{
    extern __shared__ float sm[];
    const int tid  = threadIdx.x;
    const int wid  = tid >> 5;
    const int lane = tid & 31;

    // ---- stage all weights into smem once ----
    cpf(sm + W_IN,  yWin, 128,   tid);
    cpf(sm + B_IN,  yBin, 64,    tid);
    cpf(sm + W_H,   yWh,  12288, tid);
    cpf(sm + B_H,   yBh,  192,   tid);
    cpf(sm + W_OUT, yWout, 64,   tid);
    if (tid == 0) sm[B_OUT] = yBout[0];
    float* smq = sm + NET_SZ;
    cpf(smq + W_IN,  qWin, 128,   tid);
    cpf(smq + B_IN,  qBin, 64,    tid);
    cpf(smq + W_H,   qWh,  12288, tid);
    cpf(smq + B_H,   qBh,  192,   tid);
    cpf(smq + W_OUT, qWout, 64,   tid);
    if (tid == 0) smq[B_OUT] = qBout[0];
    if (tid < 32) sm[OFF_YS + tid] = y0[0];
    __syncthreads();

    const int pbase = blockIdx.x * PPC;
    const float* HD2 = sm + OFF_HD2;

    float lossAcc = 0.0f, Ytilde = 0.0f;
    float dwcur = 0.0f;
    if (wid == 0) dwcur = dW[pbase + lane];   // prefetch step 0

    // initial fused eval at t = 0
    eval_fused(sm, 0.0f, wid, lane, tid);

    for (int n = 0; n < NSTEP; n++) {
        if (wid == 0) {
            int p = lane;
            float Yv  = HD2[p]       + HD2[32 + p]  + HD2[64 + p]  + HD2[96 + p]
                      + sm[B_OUT];
            float dYv = HD2[128 + p] + HD2[160 + p] + HD2[192 + p] + HD2[224 + p];
            float qv  = HD2[256 + p] + HD2[288 + p] + HD2[320 + p] + HD2[352 + p]
                      + smq[B_OUT];
            if (n > 0) {
                float e = Yv - Ytilde;
                lossAcc = fmaf(e, e, lossAcc);
            }
            float dwn = SQRT_DT * dwcur;
            Ytilde = Yv - qv * qv * DTV + SIGMA * dYv * dwn;
            sm[OFF_YS + p] += qv * DTV + SIGMA * dwn;
            if (n + 1 < NSTEP) dwcur = dW[(n + 1) * BATCH + pbase + p];
        }
        __syncthreads();

        eval_fused(sm, (float)(n + 1) * DTV, wid, lane, tid);
    }

    if (wid == 0) {
        int p = lane;
        float Yv  = HD2[p]       + HD2[32 + p]  + HD2[64 + p]  + HD2[96 + p]
                  + sm[B_OUT];
        float dYv = HD2[128 + p] + HD2[160 + p] + HD2[192 + p] + HD2[224 + p];
        float e = Yv - Ytilde;
        lossAcc = fmaf(e, e, lossAcc);
        float yN = sm[OFF_YS + p];
        float e1 = Yv - yN * yN;
        float e2 = dYv - 2.0f * yN;
        lossAcc = fmaf(e1, e1, fmaf(e2, e2, lossAcc));
#pragma unroll
        for (int o = 16; o > 0; o >>= 1)
            lossAcc += __shfl_down_sync(0xffffffffu, lossAcc, o);
        if (lane == 0) g_part[blockIdx.x] = lossAcc;
    }

    // ---- last-CTA deterministic reduction (single launch) ----
    if (tid == 0) {
        __threadfence();
        int old = atomicAdd(&g_count, 1);
        if (old == NCTA - 1) {
            __threadfence();
            float acc = 0.0f;
#pragma unroll 8
            for (int i = 0; i < NCTA; i++) acc += g_part[i];
            out[0] = acc * (1.0f / (float)BATCH);
            g_count = 0;
        }
    }
}

extern "C" void kernel_launch(void* const* d_in, const int* in_sizes, int n_in,
                              void* d_out, int out_size)
{
    const float *yWin, *yBin, *yWh, *yBh, *yWout, *yBout;
    const float *qWin, *qBin, *qWh, *qBh, *qWout, *qBout;
    const float *y0, *dW;

    if (in_sizes[0] == 1) {
        y0    = (const float*)d_in[0];
        yWin  = (const float*)d_in[1];
        yBin  = (const float*)d_in[2];
        yWh   = (const float*)d_in[3];
        yBh   = (const float*)d_in[4];
        yWout = (const float*)d_in[5];
        yBout = (const float*)d_in[6];
        qWin  = (const float*)d_in[7];
        qBin  = (const float*)d_in[8];
        qWh   = (const float*)d_in[9];
        qBh   = (const float*)d_in[10];
        qWout = (const float*)d_in[11];
        qBout = (const float*)d_in[12];
        dW    = (const float*)d_in[13];
    } else {
        yWin  = (const float*)d_in[0];
        yBin  = (const float*)d_in[1];
        yWh   = (const float*)d_in[2];
        yBh   = (const float*)d_in[3];
        yWout = (const float*)d_in[4];
        yBout = (const float*)d_in[5];
        qWin  = (const float*)d_in[6];
        qBin  = (const float*)d_in[7];
        qWh   = (const float*)d_in[8];
        qBh   = (const float*)d_in[9];
        qWout = (const float*)d_in[10];
        qBout = (const float*)d_in[11];
        y0    = (const float*)d_in[12];
        dW    = (const float*)d_in[13];
    }

    cudaFuncSetAttribute(fbsnn_main, cudaFuncAttributeMaxDynamicSharedMemorySize,
                         SMEM_BYTES);

    fbsnn_main<<<NCTA, NTHR, SMEM_BYTES>>>(yWin, yBin, yWh, yBh, yWout, yBout,
                                           qWin, qBin, qWh, qBh, qWout, qBout,
                                           y0, dW, (float*)d_out);
}

// round 10
// speedup vs baseline: 1.5695x; 1.5695x over previous
#include <cuda_runtime.h>

#define DTV      0.02f
#define SQRT_DT  0.141421356237309515f
#define SIGMA    0.5f
#define NSTEP    50
#define BATCH    4096
#define PPC      32            // paths per CTA
#define NCTA     (BATCH / PPC) // 128
#define NTHR     384

typedef unsigned long long u64;

// ---- shared-memory layout (float offsets) ----
#define W_IN   0       // [2][64] = 128
#define B_IN   128     // 64
#define W_H    192     // [3][64][64] = 12288
#define B_H    12480   // [3][64] = 192
#define W_OUT  12672   // 64
#define B_OUT  12736   // 1 (+3 pad)
#define NET_SZ 12740
// activations: dup'd pairs {x,x}, [64 rows][32 u64], XOR-swizzled chunks.
// Two contiguous SETS of {X, dX, QX} (12288 floats = 48KB each) so the
// K-third exchange (48KB) can overlay the DEAD output set each layer.
#define XBUF     4096
#define OFF_S0   (2 * NET_SZ)
#define OFF_S1   (OFF_S0 + 3 * XBUF)
#define OFF_YS   (OFF_S1 + 3 * XBUF)
#define OFF_HD2  (OFF_YS + 32)          // [3 heads][4 quarters][32]
#define SMEM_FLOATS (OFF_HD2 + 384)
#define SMEM_BYTES  (SMEM_FLOATS * 4)   // ~198 KB

__device__ float g_part[NCTA];
__device__ int   g_count = 0;

__device__ __forceinline__ void cpf(float* d, const float* s, int n, int tid) {
    for (int i = tid; i < n; i += NTHR) d[i] = s[i];
}

__device__ __forceinline__ u64 fma2(u64 a, u64 b, u64 c) {
    u64 d;
    asm("fma.rn.f32x2 %0, %1, %2, %3;" : "=l"(d) : "l"(a), "l"(b), "l"(c));
    return d;
}
__device__ __forceinline__ u64 add2(u64 a, u64 b) {
    u64 d;
    asm("add.rn.f32x2 %0, %1, %2;" : "=l"(d) : "l"(a), "l"(b));
    return d;
}
__device__ __forceinline__ u64 pk(float lo, float hi) {
    u64 r;
    asm("mov.b64 %0, {%1, %2};" : "=l"(r) : "f"(lo), "f"(hi));
    return r;
}
__device__ __forceinline__ void upk(u64 v, float& lo, float& hi) {
    asm("mov.b64 {%0, %1}, %2;" : "=f"(lo), "=f"(hi) : "l"(v));
}

// swizzled 16B-chunk index within a 64-row x 256B activation buffer
__device__ __forceinline__ int swz(int c, int r) { return c ^ ((r >> 2) & 15); }

// store 2 rows (rbase, rbase+1) of sin/dsin/q activations from one packed pair
__device__ __forceinline__ void epilogue_rows(
    float* __restrict__ Xn, float* __restrict__ dXn, float* __restrict__ QXn,
    int rbase, int pg, u64 ahp[4], u64 adp[4], u64 aqp[4])
{
    float h0[4], h1[4], d0v[4], d1v[4], q0[4], q1[4];
#pragma unroll
    for (int p = 0; p < 4; p++) {
        upk(ahp[p], h0[p], h1[p]);
        upk(adp[p], d0v[p], d1v[p]);
        upk(aqp[p], q0[p], q1[p]);
    }
    ulonglong2* Xn2  = (ulonglong2*)Xn;
    ulonglong2* dXn2 = (ulonglong2*)dXn;
    ulonglong2* QXn2 = (ulonglong2*)QXn;
#pragma unroll
    for (int rr = 0; rr < 2; rr++) {
        int r = rbase + rr;
        const float* hv = rr ? h1 : h0;
        const float* dv = rr ? d1v : d0v;
        const float* qv = rr ? q1 : q0;
        float s[4], c[4], sq[4];
#pragma unroll
        for (int p = 0; p < 4; p++) {
            __sincosf(hv[p], &s[p], &c[p]);
            sq[p] = __sinf(qv[p]);
        }
        int cc0 = swz(pg * 2, r);
        int cc1 = swz(pg * 2 + 1, r);
        Xn2[r * 16 + cc0] = make_ulonglong2(pk(s[0], s[0]), pk(s[1], s[1]));
        Xn2[r * 16 + cc1] = make_ulonglong2(pk(s[2], s[2]), pk(s[3], s[3]));
        float e0 = c[0] * dv[0], e1 = c[1] * dv[1];
        float e2 = c[2] * dv[2], e3 = c[3] * dv[3];
        dXn2[r * 16 + cc0] = make_ulonglong2(pk(e0, e0), pk(e1, e1));
        dXn2[r * 16 + cc1] = make_ulonglong2(pk(e2, e2), pk(e3, e3));
        QXn2[r * 16 + cc0] = make_ulonglong2(pk(sq[0], sq[0]), pk(sq[1], sq[1]));
        QXn2[r * 16 + cc1] = make_ulonglong2(pk(sq[2], sq[2]), pk(sq[3], sq[3]));
    }
}

// Fused hidden layer, 3-way K-split.
// third 0: i in [0,22), keeps pair0 (rows j0,j0+1)
// third 1: i in [22,43), keeps pair1 (rows j0+2,j0+3)
// third 2: i in [43,64), keeps nothing (donates both pairs)
// Exchange overlays the DEAD output set (out region, 48KB).
__device__ __forceinline__ void fused_layer(
    const float* __restrict__ Wy, const float* __restrict__ by,
    const float* __restrict__ Wq, const float* __restrict__ bq,
    const float* __restrict__ in_set, float* __restrict__ out_set,
    int jg, int pg, int third, int ht)
{
    const float* X   = in_set;
    const float* dXb = in_set + XBUF;
    const float* QX  = in_set + 2 * XBUF;
    float* Xn  = out_set;
    float* dXn = out_set + XBUF;
    float* QXn = out_set + 2 * XBUF;

    const ulonglong2* WY2 = (const ulonglong2*)Wy;
    const ulonglong2* WQ2 = (const ulonglong2*)Wq;
    const ulonglong2* X2  = (const ulonglong2*)X;
    const ulonglong2* dX2 = (const ulonglong2*)dXb;
    const ulonglong2* QX2 = (const ulonglong2*)QX;

    const int j0 = jg * 4;
    const int ibeg = (third == 0) ? 0  : (third == 1) ? 22 : 43;
    const int iend = (third == 0) ? 22 : (third == 1) ? 43 : 64;

    u64 ah[2][4], ad[2][4], aq[2][4];
    {
        u64 by01 = pk(by[j0], by[j0 + 1]);
        u64 by23 = pk(by[j0 + 2], by[j0 + 3]);
        u64 bq01 = pk(bq[j0], bq[j0 + 1]);
        u64 bq23 = pk(bq[j0 + 2], bq[j0 + 3]);
#pragma unroll
        for (int p = 0; p < 4; p++) {
            ah[0][p] = (third == 0) ? by01 : 0ull;
            ah[1][p] = (third == 1) ? by23 : 0ull;
            aq[0][p] = (third == 0) ? bq01 : 0ull;
            aq[1][p] = (third == 1) ? bq23 : 0ull;
            ad[0][p] = 0ull; ad[1][p] = 0ull;
        }
    }

#pragma unroll 4
    for (int i = ibeg; i < iend; i++) {
        ulonglong2 wY = WY2[i * 16 + jg];
        ulonglong2 wQ = WQ2[i * 16 + jg];
        int c0 = swz(pg * 2, i);
        int c1 = swz(pg * 2 + 1, i);
        ulonglong2 xa = X2[i * 16 + c0];
        ulonglong2 xb = X2[i * 16 + c1];
        ulonglong2 da = dX2[i * 16 + c0];
        ulonglong2 db = dX2[i * 16 + c1];
        ulonglong2 qa = QX2[i * 16 + c0];
        ulonglong2 qb = QX2[i * 16 + c1];
        u64 xd[4] = {xa.x, xa.y, xb.x, xb.y};
        u64 dd[4] = {da.x, da.y, db.x, db.y};
        u64 qd[4] = {qa.x, qa.y, qb.x, qb.y};
#pragma unroll
        for (int p = 0; p < 4; p++) {
            ah[0][p] = fma2(wY.x, xd[p], ah[0][p]);
            ah[1][p] = fma2(wY.y, xd[p], ah[1][p]);
            ad[0][p] = fma2(wY.x, dd[p], ad[0][p]);
            ad[1][p] = fma2(wY.y, dd[p], ad[1][p]);
            aq[0][p] = fma2(wQ.x, qd[p], aq[0][p]);
            aq[1][p] = fma2(wQ.y, qd[p], aq[1][p]);
        }
    }

    // ---- exchange through the dead output region ----
    // u64 row layout (rows of 128 slots):
    //  0-11 : third0's pair1   12-23: third1's pair0
    // 24-35 : third2's pair0   36-47: third2's pair1
    u64* EX = (u64*)out_set;
    if (third == 0) {
#pragma unroll
        for (int p = 0; p < 4; p++) {
            EX[(0 + p) * 128 + ht] = ah[1][p];
            EX[(4 + p) * 128 + ht] = ad[1][p];
            EX[(8 + p) * 128 + ht] = aq[1][p];
        }
    } else if (third == 1) {
#pragma unroll
        for (int p = 0; p < 4; p++) {
            EX[(12 + p) * 128 + ht] = ah[0][p];
            EX[(16 + p) * 128 + ht] = ad[0][p];
            EX[(20 + p) * 128 + ht] = aq[0][p];
        }
    } else {
#pragma unroll
        for (int p = 0; p < 4; p++) {
            EX[(24 + p) * 128 + ht] = ah[0][p];
            EX[(28 + p) * 128 + ht] = ad[0][p];
            EX[(32 + p) * 128 + ht] = aq[0][p];
            EX[(36 + p) * 128 + ht] = ah[1][p];
            EX[(40 + p) * 128 + ht] = ad[1][p];
            EX[(44 + p) * 128 + ht] = aq[1][p];
        }
    }
    __syncthreads();

    if (third == 0) {
#pragma unroll
        for (int p = 0; p < 4; p++) {
            ah[0][p] = add2(add2(ah[0][p], EX[(12 + p) * 128 + ht]),
                            EX[(24 + p) * 128 + ht]);
            ad[0][p] = add2(add2(ad[0][p], EX[(16 + p) * 128 + ht]),
                            EX[(28 + p) * 128 + ht]);
            aq[0][p] = add2(add2(aq[0][p], EX[(20 + p) * 128 + ht]),
                            EX[(32 + p) * 128 + ht]);
        }
    } else if (third == 1) {
#pragma unroll
        for (int p = 0; p < 4; p++) {
            ah[1][p] = add2(add2(ah[1][p], EX[(0 + p) * 128 + ht]),
                            EX[(36 + p) * 128 + ht]);
            ad[1][p] = add2(add2(ad[1][p], EX[(4 + p) * 128 + ht]),
                            EX[(40 + p) * 128 + ht]);
            aq[1][p] = add2(add2(aq[1][p], EX[(8 + p) * 128 + ht]),
                            EX[(44 + p) * 128 + ht]);
        }
    }
    __syncthreads();   // all exchange reads done before epilogue overwrites

    if (third == 0)
        epilogue_rows(Xn, dXn, QXn, j0, pg, ah[0], ad[0], aq[0]);
    else if (third == 1)
        epilogue_rows(Xn, dXn, QXn, j0 + 2, pg, ah[1], ad[1], aq[1]);
    __syncthreads();
}

// Fused full-net eval; ends with HD2 head partials written and CTA synced.
__device__ __forceinline__ void eval_fused(float* sm, float tval,
                                           int jg, int pg, int third, int ht,
                                           int wid, int lane, int tid)
{
    const float* netY = sm;
    const float* netQ = sm + NET_SZ;
    float* S0 = sm + OFF_S0;
    float* S1 = sm + OFF_S1;
    const float* ys = sm + OFF_YS;

    // ---- input layer into set0 (all 384 threads) ----
    {
        ulonglong2* X2  = (ulonglong2*)S0;
        ulonglong2* dX2 = (ulonglong2*)(S0 + XBUF);
        ulonglong2* QX2 = (ulonglong2*)(S0 + 2 * XBUF);
        // Y tasks: (row r, pathquad pq) -> X, dX
        for (int u = tid; u < 512; u += NTHR) {
            int r = u >> 3, pq = u & 7, p0 = pq * 4;
            float wtY = netY[W_IN + r], wyY = netY[W_IN + 64 + r];
            float tbY = fmaf(tval, wtY, netY[B_IN + r]);
            float s[4], c[4];
#pragma unroll
            for (int p = 0; p < 4; p++)
                __sincosf(fmaf(ys[p0 + p], wyY, tbY), &s[p], &c[p]);
            int cc0 = swz(pq * 2, r), cc1 = swz(pq * 2 + 1, r);
            X2[r * 16 + cc0] = make_ulonglong2(pk(s[0], s[0]), pk(s[1], s[1]));
            X2[r * 16 + cc1] = make_ulonglong2(pk(s[2], s[2]), pk(s[3], s[3]));
            float d0 = c[0] * wyY, d1 = c[1] * wyY, d2 = c[2] * wyY, d3 = c[3] * wyY;
            dX2[r * 16 + cc0] = make_ulonglong2(pk(d0, d0), pk(d1, d1));
            dX2[r * 16 + cc1] = make_ulonglong2(pk(d2, d2), pk(d3, d3));
        }
        // q tasks
        for (int u = tid; u < 512; u += NTHR) {
            int r = u >> 3, pq = u & 7, p0 = pq * 4;
            float wtQ = netQ[W_IN + r], wyQ = netQ[W_IN + 64 + r];
            float tbQ = fmaf(tval, wtQ, netQ[B_IN + r]);
            float sq[4];
#pragma unroll
            for (int p = 0; p < 4; p++)
                sq[p] = __sinf(fmaf(ys[p0 + p], wyQ, tbQ));
            int cc0 = swz(pq * 2, r), cc1 = swz(pq * 2 + 1, r);
            QX2[r * 16 + cc0] = make_ulonglong2(pk(sq[0], sq[0]), pk(sq[1], sq[1]));
            QX2[r * 16 + cc1] = make_ulonglong2(pk(sq[2], sq[2]), pk(sq[3], sq[3]));
        }
    }
    __syncthreads();

    fused_layer(netY + W_H,        netY + B_H,       netQ + W_H,        netQ + B_H,
                S0, S1, jg, pg, third, ht);
    fused_layer(netY + W_H + 4096, netY + B_H + 64,  netQ + W_H + 4096, netQ + B_H + 64,
                S1, S0, jg, pg, third, ht);
    fused_layer(netY + W_H + 8192, netY + B_H + 128, netQ + W_H + 8192, netQ + B_H + 128,
                S0, S1, jg, pg, third, ht);

    // ---- head partials: 12 warps = 3 heads x 4 i-quarters (outputs in S1) ----
    if (wid < 12) {
        int head = wid >> 2, quarter = wid & 3;
        const float* src = S1 + head * XBUF;               // Xn | dXn | QXn
        const float* wv  = (head == 2) ? (netQ + W_OUT) : (netY + W_OUT);
        int p = lane;
        int i0 = quarter * 16;
        float a0 = 0.0f, a1 = 0.0f, a2 = 0.0f, a3 = 0.0f;
#pragma unroll
        for (int i = 0; i < 16; i += 4) {
#pragma unroll
            for (int k = 0; k < 4; k++) {
                int ii = i0 + i + k;
                int ch = swz(p >> 1, ii);
                int off = ii * 64 + ch * 4 + (p & 1) * 2;  // lo of dup pair
                float v = src[off] * wv[ii];
                if (k == 0) a0 += v; else if (k == 1) a1 += v;
                else if (k == 2) a2 += v; else a3 += v;
            }
        }
        sm[OFF_HD2 + head * 128 + quarter * 32 + p] = (a0 + a1) + (a2 + a3);
    }
    __syncthreads();
}

__global__ __launch_bounds__(NTHR, 1) void fbsnn_main(
    const float* __restrict__ yWin,  const float* __restrict__ yBin,
    const float* __restrict__ yWh,   const float* __restrict__ yBh,
    const float* __restrict__ yWout, const float* __restrict__ yBout,
    const float* __restrict__ qWin,  const float* __restrict__ qBin,
    const float* __restrict__ qWh,   const float* __restrict__ qBh,
    const float* __restrict__ qWout, const float* __restrict__ qBout,
    const float* __restrict__ y0,    const float* __restrict__ dW,
    float* __restrict__ out)
{
    extern __shared__ float sm[];
    const int tid   = threadIdx.x;
    const int wid   = tid >> 5;
    const int lane  = tid & 31;
    const int third = tid >> 7;     // 3 K-thirds
    const int ht    = tid & 127;
    const int jg    = ht & 15;
    const int pg    = ht >> 4;

    // ---- stage all weights into smem once ----
    cpf(sm + W_IN,  yWin, 128,   tid);
    cpf(sm + B_IN,  yBin, 64,    tid);
    cpf(sm + W_H,   yWh,  12288, tid);
    cpf(sm + B_H,   yBh,  192,   tid);
    cpf(sm + W_OUT, yWout, 64,   tid);
    if (tid == 0) sm[B_OUT] = yBout[0];
    float* smq = sm + NET_SZ;
    cpf(smq + W_IN,  qWin, 128,   tid);
    cpf(smq + B_IN,  qBin, 64,    tid);
    cpf(smq + W_H,   qWh,  12288, tid);
    cpf(smq + B_H,   qBh,  192,   tid);
    cpf(smq + W_OUT, qWout, 64,   tid);
    if (tid == 0) smq[B_OUT] = qBout[0];
    if (tid < 32) sm[OFF_YS + tid] = y0[0];
    __syncthreads();

    const int pbase = blockIdx.x * PPC;
    const float* HD2 = sm + OFF_HD2;

    float lossAcc = 0.0f, Ytilde = 0.0f;
    float dwcur = 0.0f;
    if (wid == 0) dwcur = dW[pbase + lane];   // prefetch step 0

    // initial fused eval at t = 0
    eval_fused(sm, 0.0f, jg, pg, third, ht, wid, lane, tid);

    for (int n = 0; n < NSTEP; n++) {
        if (wid == 0) {
            int p = lane;
            float Yv  = HD2[p]       + HD2[32 + p]  + HD2[64 + p]  + HD2[96 + p]
                      + sm[B_OUT];
            float dYv = HD2[128 + p] + HD2[160 + p] + HD2[192 + p] + HD2[224 + p];
            float qv  = HD2[256 + p] + HD2[288 + p] + HD2[320 + p] + HD2[352 + p]
                      + smq[B_OUT];
            if (n > 0) {
                float e = Yv - Ytilde;
                lossAcc = fmaf(e, e, lossAcc);
            }
            float dwn = SQRT_DT * dwcur;
            Ytilde = Yv - qv * qv * DTV + SIGMA * dYv * dwn;
            sm[OFF_YS + p] += qv * DTV + SIGMA * dwn;
            if (n + 1 < NSTEP) dwcur = dW[(n + 1) * BATCH + pbase + p];
        }
        __syncthreads();

        eval_fused(sm, (float)(n + 1) * DTV, jg, pg, third, ht, wid, lane, tid);
    }

    if (wid == 0) {
        int p = lane;
        float Yv  = HD2[p]       + HD2[32 + p]  + HD2[64 + p]  + HD2[96 + p]
                  + sm[B_OUT];
        float dYv = HD2[128 + p] + HD2[160 + p] + HD2[192 + p] + HD2[224 + p];
        float e = Yv - Ytilde;
        lossAcc = fmaf(e, e, lossAcc);
        float yN = sm[OFF_YS + p];
        float e1 = Yv - yN * yN;
        float e2 = dYv - 2.0f * yN;
        lossAcc = fmaf(e1, e1, fmaf(e2, e2, lossAcc));
#pragma unroll
        for (int o = 16; o > 0; o >>= 1)
            lossAcc += __shfl_down_sync(0xffffffffu, lossAcc, o);
        if (lane == 0) g_part[blockIdx.x] = lossAcc;
    }

    // ---- last-CTA deterministic reduction (single launch) ----
    if (tid == 0) {
        __threadfence();
        int old = atomicAdd(&g_count, 1);
        if (old == NCTA - 1) {
            __threadfence();
            float acc = 0.0f;
#pragma unroll 8
            for (int i = 0; i < NCTA; i++) acc += g_part[i];
            out[0] = acc * (1.0f / (float)BATCH);
            g_count = 0;
        }
    }
}

extern "C" void kernel_launch(void* const* d_in, const int* in_sizes, int n_in,
                              void* d_out, int out_size)
{
    const float *yWin, *yBin, *yWh, *yBh, *yWout, *yBout;
    const float *qWin, *qBin, *qWh, *qBh, *qWout, *qBout;
    const float *y0, *dW;

    if (in_sizes[0] == 1) {
        y0    = (const float*)d_in[0];
        yWin  = (const float*)d_in[1];
        yBin  = (const float*)d_in[2];
        yWh   = (const float*)d_in[3];
        yBh   = (const float*)d_in[4];
        yWout = (const float*)d_in[5];
        yBout = (const float*)d_in[6];
        qWin  = (const float*)d_in[7];
        qBin  = (const float*)d_in[8];
        qWh   = (const float*)d_in[9];
        qBh   = (const float*)d_in[10];
        qWout = (const float*)d_in[11];
        qBout = (const float*)d_in[12];
        dW    = (const float*)d_in[13];
    } else {
        yWin  = (const float*)d_in[0];
        yBin  = (const float*)d_in[1];
        yWh   = (const float*)d_in[2];
        yBh   = (const float*)d_in[3];
        yWout = (const float*)d_in[4];
        yBout = (const float*)d_in[5];
        qWin  = (const float*)d_in[6];
        qBin  = (const float*)d_in[7];
        qWh   = (const float*)d_in[8];
        qBh   = (const float*)d_in[9];
        qWout = (const float*)d_in[10];
        qBout = (const float*)d_in[11];
        y0    = (const float*)d_in[12];
        dW    = (const float*)d_in[13];
    }

    cudaFuncSetAttribute(fbsnn_main, cudaFuncAttributeMaxDynamicSharedMemorySize,
                         SMEM_BYTES);

    fbsnn_main<<<NCTA, NTHR, SMEM_BYTES>>>(yWin, yBin, yWh, yBh, yWout, yBout,
                                           qWin, qBin, qWh, qBh, qWout, qBout,
                                           y0, dW, (float*)d_out);
}

// round 12
// speedup vs baseline: 1.8632x; 1.1871x over previous
#include <cuda_runtime.h>

#define DTV      0.02f
#define SQRT_DT  0.141421356237309515f
#define SIGMA    0.5f
#define NSTEP    50
#define BATCH    4096
#define PPC      32            // paths per CTA
#define NCTA     (BATCH / PPC) // 128
#define NTHR     256

typedef unsigned long long u64;

// ---- shared-memory layout (float offsets) ----
#define W_IN   0       // [2][64] = 128
#define B_IN   128     // 64
#define W_H    192     // [3][64][64] = 12288
#define B_H    12480   // [3][64] = 192
#define W_OUT  12672   // 64
#define B_OUT  12736   // 1 (+3 pad)
#define NET_SZ 12740
// activations: duplicated pairs {x,x}, [64 rows][32 u64], XOR-swizzled chunks
#define XBUF     4096
#define OFF_X    (2 * NET_SZ)
#define OFF_DX   (OFF_X   + XBUF)
#define OFF_XN   (OFF_DX  + XBUF)
#define OFF_DXN  (OFF_XN  + XBUF)
#define OFF_QX   (OFF_DXN + XBUF)
#define OFF_QXN  (OFF_QX  + XBUF)
// K-split partial exchange buffers: [12][128] u64 each
#define OFF_PX   (OFF_QXN + XBUF)     // A's pair1 partials (3072 floats)
#define OFF_PY   (OFF_PX  + 3072)    // B's pair0 partials
#define OFF_YS   (OFF_PY  + 3072)
#define OFF_HD2  (OFF_YS  + 32)       // [2][96] head partials
#define OFF_HD   (OFF_HD2 + 192)      // 96 floats: Y | dY | q
#define SMEM_FLOATS (OFF_HD + 96)
#define SMEM_BYTES  (SMEM_FLOATS * 4)

__device__ float g_part[NCTA];
__device__ int   g_count = 0;

__device__ __forceinline__ void cpf(float* d, const float* s, int n, int tid) {
    for (int i = tid; i < n; i += NTHR) d[i] = s[i];
}

__device__ __forceinline__ u64 fma2(u64 a, u64 b, u64 c) {
    u64 d;
    asm("fma.rn.f32x2 %0, %1, %2, %3;" : "=l"(d) : "l"(a), "l"(b), "l"(c));
    return d;
}
__device__ __forceinline__ u64 add2(u64 a, u64 b) {
    u64 d;
    asm("add.rn.f32x2 %0, %1, %2;" : "=l"(d) : "l"(a), "l"(b));
    return d;
}
__device__ __forceinline__ u64 pk(float lo, float hi) {
    u64 r;
    asm("mov.b64 %0, {%1, %2};" : "=l"(r) : "f"(lo), "f"(hi));
    return r;
}
__device__ __forceinline__ void upk(u64 v, float& lo, float& hi) {
    asm("mov.b64 {%0, %1}, %2;" : "=f"(lo), "=f"(hi) : "l"(v));
}

// swizzled 16B-chunk index within a 64-row x 256B activation buffer
__device__ __forceinline__ int swz(int c, int r) { return c ^ ((r >> 2) & 15); }

// store 2 rows (rbase, rbase+1) of sin/dsin/sin(q) activations
__device__ __forceinline__ void epilogue_rows(
    float* __restrict__ Xn, float* __restrict__ dXn, float* __restrict__ QXn,
    int rbase, int pg, u64 ahp[4], u64 adp[4], u64 aqp[4])
{
    float h0[4], h1[4], d0v[4], d1v[4], q0[4], q1[4];
#pragma unroll
    for (int p = 0; p < 4; p++) {
        upk(ahp[p], h0[p], h1[p]);
        upk(adp[p], d0v[p], d1v[p]);
        upk(aqp[p], q0[p], q1[p]);
    }
    ulonglong2* Xn2  = (ulonglong2*)Xn;
    ulonglong2* dXn2 = (ulonglong2*)dXn;
    ulonglong2* QXn2 = (ulonglong2*)QXn;
#pragma unroll
    for (int rr = 0; rr < 2; rr++) {
        int r = rbase + rr;
        const float* hv = rr ? h1 : h0;
        const float* dv = rr ? d1v : d0v;
        const float* qv = rr ? q1 : q0;
        float s[4], c[4], sq[4];
#pragma unroll
        for (int p = 0; p < 4; p++) {
            __sincosf(hv[p], &s[p], &c[p]);
            sq[p] = __sinf(qv[p]);
        }
        int cc0 = swz(pg * 2, r);
        int cc1 = swz(pg * 2 + 1, r);
        Xn2[r * 16 + cc0] = make_ulonglong2(pk(s[0], s[0]), pk(s[1], s[1]));
        Xn2[r * 16 + cc1] = make_ulonglong2(pk(s[2], s[2]), pk(s[3], s[3]));
        float e0 = c[0] * dv[0], e1 = c[1] * dv[1];
        float e2 = c[2] * dv[2], e3 = c[3] * dv[3];
        dXn2[r * 16 + cc0] = make_ulonglong2(pk(e0, e0), pk(e1, e1));
        dXn2[r * 16 + cc1] = make_ulonglong2(pk(e2, e2), pk(e3, e3));
        QXn2[r * 16 + cc0] = make_ulonglong2(pk(sq[0], sq[0]), pk(sq[1], sq[1]));
        QXn2[r * 16 + cc1] = make_ulonglong2(pk(sq[2], sq[2]), pk(sq[3], sq[3]));
    }
}

// Fused hidden layer, K-split across the two thread halves.
// half A (tid<128): i in [0,32);  half B: i in [32,64).
// TWO passes over the i-range: pass A = h+dh (16 acc), pass B = q (8 acc) —
// smaller live set per loop lets ptxas pipeline the LDS ahead of the FMAs.
// Swizzle hoisted: (i>>2)&15 is constant within each 4-i group.
__device__ __forceinline__ void fused_layer(
    float* __restrict__ sm,
    const float* __restrict__ Wy, const float* __restrict__ by,
    const float* __restrict__ Wq, const float* __restrict__ bq,
    const float* __restrict__ X,  const float* __restrict__ dXb,
    const float* __restrict__ QX,
    float* __restrict__ Xn, float* __restrict__ dXn, float* __restrict__ QXn,
    int jg, int pg, int half, int ht)
{
    const ulonglong2* WY2 = (const ulonglong2*)Wy;
    const ulonglong2* WQ2 = (const ulonglong2*)Wq;
    const ulonglong2* X2  = (const ulonglong2*)X;
    const ulonglong2* dX2 = (const ulonglong2*)dXb;
    const ulonglong2* QX2 = (const ulonglong2*)QX;

    const int j0 = jg * 4;
    const int igbase = half * 8;          // 8 groups of 4 i per half

    u64 ah[2][4], ad[2][4];
    {
        u64 by01 = pk(by[j0], by[j0 + 1]);
        u64 by23 = pk(by[j0 + 2], by[j0 + 3]);
#pragma unroll
        for (int p = 0; p < 4; p++) {
            ah[0][p] = half ? 0ull : by01;
            ah[1][p] = half ? by23 : 0ull;
            ad[0][p] = 0ull; ad[1][p] = 0ull;
        }
    }

    // ---- pass A: h + dh ----
#pragma unroll
    for (int ig = 0; ig < 8; ig++) {
        const int sw = igbase + ig;       // (i>>2)&15, constant in group
        const int c0 = (pg * 2) ^ sw;
        const int c1 = (pg * 2 + 1) ^ sw;
        const int i0 = sw * 4;            // = half*32 + ig*4
#pragma unroll
        for (int k = 0; k < 4; k++) {
            int i = i0 + k;
            ulonglong2 wY = WY2[i * 16 + jg];
            ulonglong2 xa = X2[i * 16 + c0];
            ulonglong2 xb = X2[i * 16 + c1];
            ulonglong2 da = dX2[i * 16 + c0];
            ulonglong2 db = dX2[i * 16 + c1];
            u64 xd[4] = {xa.x, xa.y, xb.x, xb.y};
            u64 dd[4] = {da.x, da.y, db.x, db.y};
#pragma unroll
            for (int p = 0; p < 4; p++) {
                ah[0][p] = fma2(wY.x, xd[p], ah[0][p]);
                ah[1][p] = fma2(wY.y, xd[p], ah[1][p]);
                ad[0][p] = fma2(wY.x, dd[p], ad[0][p]);
                ad[1][p] = fma2(wY.y, dd[p], ad[1][p]);
            }
        }
    }

    // ---- pass B: q ----
    u64 aq[2][4];
    {
        u64 bq01 = pk(bq[j0], bq[j0 + 1]);
        u64 bq23 = pk(bq[j0 + 2], bq[j0 + 3]);
#pragma unroll
        for (int p = 0; p < 4; p++) {
            aq[0][p] = half ? 0ull : bq01;
            aq[1][p] = half ? bq23 : 0ull;
        }
    }
#pragma unroll
    for (int ig = 0; ig < 8; ig++) {
        const int sw = igbase + ig;
        const int c0 = (pg * 2) ^ sw;
        const int c1 = (pg * 2 + 1) ^ sw;
        const int i0 = sw * 4;
#pragma unroll
        for (int k = 0; k < 4; k++) {
            int i = i0 + k;
            ulonglong2 wQ = WQ2[i * 16 + jg];
            ulonglong2 qa = QX2[i * 16 + c0];
            ulonglong2 qb = QX2[i * 16 + c1];
            u64 qd[4] = {qa.x, qa.y, qb.x, qb.y};
#pragma unroll
            for (int p = 0; p < 4; p++) {
                aq[0][p] = fma2(wQ.x, qd[p], aq[0][p]);
                aq[1][p] = fma2(wQ.y, qd[p], aq[1][p]);
            }
        }
    }

    // ---- partial exchange: A gives pair1, B gives pair0 ----
    u64* PX = (u64*)(sm + OFF_PX);   // written by A
    u64* PY = (u64*)(sm + OFF_PY);   // written by B
    if (half == 0) {
#pragma unroll
        for (int p = 0; p < 4; p++) {
            PX[(0 + p) * 128 + ht] = ah[1][p];
            PX[(4 + p) * 128 + ht] = ad[1][p];
            PX[(8 + p) * 128 + ht] = aq[1][p];
        }
    } else {
#pragma unroll
        for (int p = 0; p < 4; p++) {
            PY[(0 + p) * 128 + ht] = ah[0][p];
            PY[(4 + p) * 128 + ht] = ad[0][p];
            PY[(8 + p) * 128 + ht] = aq[0][p];
        }
    }
    __syncthreads();
    if (half == 0) {
#pragma unroll
        for (int p = 0; p < 4; p++) {
            ah[0][p] = add2(ah[0][p], PY[(0 + p) * 128 + ht]);
            ad[0][p] = add2(ad[0][p], PY[(4 + p) * 128 + ht]);
            aq[0][p] = add2(aq[0][p], PY[(8 + p) * 128 + ht]);
        }
        epilogue_rows(Xn, dXn, QXn, j0, pg, ah[0], ad[0], aq[0]);
    } else {
#pragma unroll
        for (int p = 0; p < 4; p++) {
            ah[1][p] = add2(ah[1][p], PX[(0 + p) * 128 + ht]);
            ad[1][p] = add2(ad[1][p], PX[(4 + p) * 128 + ht]);
            aq[1][p] = add2(aq[1][p], PX[(8 + p) * 128 + ht]);
        }
        epilogue_rows(Xn, dXn, QXn, j0 + 2, pg, ah[1], ad[1], aq[1]);
    }
    __syncthreads();
}

// Fused full-net eval; ends with HD written and CTA synced.
__device__ __forceinline__ void eval_fused(float* sm, float tval,
                                           int jg, int pg, int half, int ht,
                                           int tid)
{
    const float* netY = sm;
    const float* netQ = sm + NET_SZ;
    float* X   = sm + OFF_X;
    float* dXb = sm + OFF_DX;
    float* Xn  = sm + OFF_XN;
    float* dXn = sm + OFF_DXN;
    float* QX  = sm + OFF_QX;
    float* QXn = sm + OFF_QXN;
    const float* ys = sm + OFF_YS;

    const int j0 = jg * 4, p0 = pg * 4;

    // ---- input layer ----
    {
        ulonglong2* X2  = (ulonglong2*)X;
        ulonglong2* dX2 = (ulonglong2*)dXb;
        ulonglong2* QX2 = (ulonglong2*)QX;
        float yv[4] = {ys[p0], ys[p0 + 1], ys[p0 + 2], ys[p0 + 3]};
#pragma unroll
        for (int jj = 0; jj < 2; jj++) {
            int r = j0 + half * 2 + jj;
            float wtY = netY[W_IN + r], wyY = netY[W_IN + 64 + r];
            float tbY = fmaf(tval, wtY, netY[B_IN + r]);
            float wtQ = netQ[W_IN + r], wyQ = netQ[W_IN + 64 + r];
            float tbQ = fmaf(tval, wtQ, netQ[B_IN + r]);
            float s[4], c[4], sq[4];
#pragma unroll
            for (int p = 0; p < 4; p++) {
                __sincosf(fmaf(yv[p], wyY, tbY), &s[p], &c[p]);
                sq[p] = __sinf(fmaf(yv[p], wyQ, tbQ));
            }
            int cc0 = swz(pg * 2, r);
            int cc1 = swz(pg * 2 + 1, r);
            X2[r * 16 + cc0] = make_ulonglong2(pk(s[0], s[0]), pk(s[1], s[1]));
            X2[r * 16 + cc1] = make_ulonglong2(pk(s[2], s[2]), pk(s[3], s[3]));
            float d0 = c[0] * wyY, d1 = c[1] * wyY, d2 = c[2] * wyY, d3 = c[3] * wyY;
            dX2[r * 16 + cc0] = make_ulonglong2(pk(d0, d0), pk(d1, d1));
            dX2[r * 16 + cc1] = make_ulonglong2(pk(d2, d2), pk(d3, d3));
            QX2[r * 16 + cc0] = make_ulonglong2(pk(sq[0], sq[0]), pk(sq[1], sq[1]));
            QX2[r * 16 + cc1] = make_ulonglong2(pk(sq[2], sq[2]), pk(sq[3], sq[3]));
        }
    }
    __syncthreads();
    fused_layer(sm, netY + W_H,        netY + B_H,       netQ + W_H,        netQ + B_H,
                X, dXb, QX, Xn, dXn, QXn, jg, pg, half, ht);
    fused_layer(sm, netY + W_H + 4096, netY + B_H + 64,  netQ + W_H + 4096, netQ + B_H + 64,
                Xn, dXn, QXn, X, dXb, QX, jg, pg, half, ht);
    fused_layer(sm, netY + W_H + 8192, netY + B_H + 128, netQ + W_H + 8192, netQ + B_H + 128,
                X, dXb, QX, Xn, dXn, QXn, jg, pg, half, ht);

    // ---- output heads, i-split: A warps 0-2 do i<32, B warps 4-6 do i>=32 ----
    const int wid = tid >> 5, lane = tid & 31;
    float* HD2 = sm + OFF_HD2;
    float* HD  = sm + OFF_HD;
    int hw = wid & 3;
    if (hw < 3) {
        const float* src = (hw == 0) ? Xn : (hw == 1) ? dXn : QXn;
        const float* wv  = (hw == 2) ? (netQ + W_OUT) : (netY + W_OUT);
        int i0 = half * 32;
        float a0 = 0.0f, a1 = 0.0f, a2 = 0.0f, a3 = 0.0f;
        int p = lane;
#pragma unroll 4
        for (int i = 0; i < 32; i += 4) {
#pragma unroll
            for (int k = 0; k < 4; k++) {
                int ii = i0 + i + k;
                int ch = swz(p >> 1, ii);
                int off = ii * 64 + ch * 4 + (p & 1) * 2;
                float v = src[off] * wv[ii];
                if (k == 0) a0 += v; else if (k == 1) a1 += v;
                else if (k == 2) a2 += v; else a3 += v;
            }
        }
        HD2[half * 96 + hw * 32 + lane] = (a0 + a1) + (a2 + a3);
    }
    __syncthreads();
    if (tid < 96) {
        int head = tid >> 5;
        float bias = (head == 0) ? netY[B_OUT] : (head == 2) ? netQ[B_OUT] : 0.0f;
        HD[tid] = HD2[tid] + HD2[96 + tid] + bias;
    }
    __syncthreads();
}

__global__ __launch_bounds__(NTHR, 1) void fbsnn_main(
    const float* __restrict__ yWin,  const float* __restrict__ yBin,
    const float* __restrict__ yWh,   const float* __restrict__ yBh,
    const float* __restrict__ yWout, const float* __restrict__ yBout,
    const float* __restrict__ qWin,  const float* __restrict__ qBin,
    const float* __restrict__ qWh,   const float* __restrict__ qBh,
    const float* __restrict__ qWout, const float* __restrict__ qBout,
    const float* __restrict__ y0,    const float* __restrict__ dW,
    float* __restrict__ out)
{
    extern __shared__ float sm[];
    const int tid = threadIdx.x;
    const int half = tid >> 7;
    const int ht = tid & 127;
    const int jg = ht & 15;
    const int pg = ht >> 4;

    // ---- stage all weights into smem once ----
    cpf(sm + W_IN,  yWin, 128,   tid);
    cpf(sm + B_IN,  yBin, 64,    tid);
    cpf(sm + W_H,   yWh,  12288, tid);
    cpf(sm + B_H,   yBh,  192,   tid);
    cpf(sm + W_OUT, yWout, 64,   tid);
    if (tid == 0) sm[B_OUT] = yBout[0];
    float* smq = sm + NET_SZ;
    cpf(smq + W_IN,  qWin, 128,   tid);
    cpf(smq + B_IN,  qBin, 64,    tid);
    cpf(smq + W_H,   qWh,  12288, tid);
    cpf(smq + B_H,   qBh,  192,   tid);
    cpf(smq + W_OUT, qWout, 64,   tid);
    if (tid == 0) smq[B_OUT] = qBout[0];
    if (tid < 32) sm[OFF_YS + tid] = y0[0];
    __syncthreads();

    float lossAcc = 0.0f, Ytilde = 0.0f;
    const int pbase = blockIdx.x * PPC;
    float* HD = sm + OFF_HD;

    // initial fused eval at t = 0: gives Y0, dY0, q0
    eval_fused(sm, 0.0f, jg, pg, half, ht, tid);

    for (int n = 0; n < NSTEP; n++) {
        if (tid < 32) {
            float Yc  = HD[tid];
            float dYv = HD[32 + tid];
            float qv  = HD[64 + tid];
            float dwn = SQRT_DT * dW[n * BATCH + pbase + tid];
            Ytilde = Yc - qv * qv * DTV + SIGMA * dYv * dwn;
            sm[OFF_YS + tid] += qv * DTV + SIGMA * dwn;
        }
        __syncthreads();

        eval_fused(sm, (float)(n + 1) * DTV, jg, pg, half, ht, tid);

        if (tid < 32) {
            float e = HD[tid] - Ytilde;
            lossAcc = fmaf(e, e, lossAcc);
        }
    }

    if (tid < 32) {
        float yN = sm[OFF_YS + tid];
        float e1 = HD[tid]      - yN * yN;   // terminal value residual
        float e2 = HD[32 + tid] - 2.0f * yN; // terminal gradient residual
        lossAcc = fmaf(e1, e1, fmaf(e2, e2, lossAcc));
#pragma unroll
        for (int o = 16; o > 0; o >>= 1)
            lossAcc += __shfl_down_sync(0xffffffffu, lossAcc, o);
        if (tid == 0) g_part[blockIdx.x] = lossAcc;
    }

    // ---- last-CTA deterministic reduction (single-launch design) ----
    if (tid == 0) {
        __threadfence();
        int old = atomicAdd(&g_count, 1);
        if (old == NCTA - 1) {
            __threadfence();
            float acc = 0.0f;
#pragma unroll 8
            for (int i = 0; i < NCTA; i++) acc += g_part[i];
            out[0] = acc * (1.0f / (float)BATCH);
            g_count = 0;
        }
    }
}

extern "C" void kernel_launch(void* const* d_in, const int* in_sizes, int n_in,
                              void* d_out, int out_size)
{
    const float *yWin, *yBin, *yWh, *yBh, *yWout, *yBout;
    const float *qWin, *qBin, *qWh, *qBh, *qWout, *qBout;
    const float *y0, *dW;

    if (in_sizes[0] == 1) {
        y0    = (const float*)d_in[0];
        yWin  = (const float*)d_in[1];
        yBin  = (const float*)d_in[2];
        yWh   = (const float*)d_in[3];
        yBh   = (const float*)d_in[4];
        yWout = (const float*)d_in[5];
        yBout = (const float*)d_in[6];
        qWin  = (const float*)d_in[7];
        qBin  = (const float*)d_in[8];
        qWh   = (const float*)d_in[9];
        qBh   = (const float*)d_in[10];
        qWout = (const float*)d_in[11];
        qBout = (const float*)d_in[12];
        dW    = (const float*)d_in[13];
    } else {
        yWin  = (const float*)d_in[0];
        yBin  = (const float*)d_in[1];
        yWh   = (const float*)d_in[2];
        yBh   = (const float*)d_in[3];
        yWout = (const float*)d_in[4];
        yBout = (const float*)d_in[5];
        qWin  = (const float*)d_in[6];
        qBin  = (const float*)d_in[7];
        qWh   = (const float*)d_in[8];
        qBh   = (const float*)d_in[9];
        qWout = (const float*)d_in[10];
        qBout = (const float*)d_in[11];
        y0    = (const float*)d_in[12];
        dW    = (const float*)d_in[13];
    }

    cudaFuncSetAttribute(fbsnn_main, cudaFuncAttributeMaxDynamicSharedMemorySize,
                         SMEM_BYTES);

    fbsnn_main<<<NCTA, NTHR, SMEM_BYTES>>>(yWin, yBin, yWh, yBh, yWout, yBout,
                                           qWin, qBin, qWh, qBh, qWout, qBout,
                                           y0, dW, (float*)d_out);
}

// round 13
// speedup vs baseline: 1.8709x; 1.0041x over previous
#include <cuda_runtime.h>

#define DTV      0.02f
#define SQRT_DT  0.141421356237309515f
#define SIGMA    0.5f
#define NSTEP    50
#define BATCH    4096
#define PPC      32            // paths per CTA
#define NCTA     (BATCH / PPC) // 128
#define NTHR     256

typedef unsigned long long u64;

// ---- shared-memory layout (float offsets) ----
#define W_IN   0       // [2][64] = 128
#define B_IN   128     // 64
#define W_H    192     // [3][64][64] = 12288
#define B_H    12480   // [3][64] = 192
#define W_OUT  12672   // 64
#define B_OUT  12736   // 1 (+3 pad)
#define NET_SZ 12740
// activations: duplicated pairs {x,x}, [64 rows][32 u64], XOR-swizzled chunks
#define XBUF     4096
#define OFF_X    (2 * NET_SZ)
#define OFF_DX   (OFF_X   + XBUF)
#define OFF_XN   (OFF_DX  + XBUF)
#define OFF_DXN  (OFF_XN  + XBUF)
#define OFF_QX   (OFF_DXN + XBUF)
#define OFF_QXN  (OFF_QX  + XBUF)
// K-split partial exchange buffers: [12][128] u64 each
#define OFF_PX   (OFF_QXN + XBUF)     // A's pair1 partials (3072 floats)
#define OFF_PY   (OFF_PX  + 3072)    // B's pair0 partials
#define OFF_YS   (OFF_PY  + 3072)
#define OFF_HD2  (OFF_YS  + 32)       // [2][96] head partials
#define OFF_HD   (OFF_HD2 + 192)      // 96 floats: Y | dY | q
#define SMEM_FLOATS (OFF_HD + 96)
#define SMEM_BYTES  (SMEM_FLOATS * 4)

__device__ float g_part[NCTA];
__device__ int   g_count = 0;

__device__ __forceinline__ void cpf(float* d, const float* s, int n, int tid) {
    for (int i = tid; i < n; i += NTHR) d[i] = s[i];
}

__device__ __forceinline__ u64 fma2(u64 a, u64 b, u64 c) {
    u64 d;
    asm("fma.rn.f32x2 %0, %1, %2, %3;" : "=l"(d) : "l"(a), "l"(b), "l"(c));
    return d;
}
__device__ __forceinline__ u64 add2(u64 a, u64 b) {
    u64 d;
    asm("add.rn.f32x2 %0, %1, %2;" : "=l"(d) : "l"(a), "l"(b));
    return d;
}
__device__ __forceinline__ u64 pk(float lo, float hi) {
    u64 r;
    asm("mov.b64 %0, {%1, %2};" : "=l"(r) : "f"(lo), "f"(hi));
    return r;
}
__device__ __forceinline__ void upk(u64 v, float& lo, float& hi) {
    asm("mov.b64 {%0, %1}, %2;" : "=f"(lo), "=f"(hi) : "l"(v));
}

// swizzled 16B-chunk index within a 64-row x 256B activation buffer
__device__ __forceinline__ int swz(int c, int r) { return c ^ ((r >> 2) & 15); }

// store 2 rows (rbase, rbase+1) of sin/dsin/sin(q) activations
__device__ __forceinline__ void epilogue_rows(
    float* __restrict__ Xn, float* __restrict__ dXn, float* __restrict__ QXn,
    int rbase, int pg, u64 ahp[4], u64 adp[4], u64 aqp[4])
{
    float h0[4], h1[4], d0v[4], d1v[4], q0[4], q1[4];
#pragma unroll
    for (int p = 0; p < 4; p++) {
        upk(ahp[p], h0[p], h1[p]);
        upk(adp[p], d0v[p], d1v[p]);
        upk(aqp[p], q0[p], q1[p]);
    }
    ulonglong2* Xn2  = (ulonglong2*)Xn;
    ulonglong2* dXn2 = (ulonglong2*)dXn;
    ulonglong2* QXn2 = (ulonglong2*)QXn;
#pragma unroll
    for (int rr = 0; rr < 2; rr++) {
        int r = rbase + rr;
        const float* hv = rr ? h1 : h0;
        const float* dv = rr ? d1v : d0v;
        const float* qv = rr ? q1 : q0;
        float s[4], c[4], sq[4];
#pragma unroll
        for (int p = 0; p < 4; p++) {
            __sincosf(hv[p], &s[p], &c[p]);
            sq[p] = __sinf(qv[p]);
        }
        int cc0 = swz(pg * 2, r);
        int cc1 = swz(pg * 2 + 1, r);
        Xn2[r * 16 + cc0] = make_ulonglong2(pk(s[0], s[0]), pk(s[1], s[1]));
        Xn2[r * 16 + cc1] = make_ulonglong2(pk(s[2], s[2]), pk(s[3], s[3]));
        float e0 = c[0] * dv[0], e1 = c[1] * dv[1];
        float e2 = c[2] * dv[2], e3 = c[3] * dv[3];
        dXn2[r * 16 + cc0] = make_ulonglong2(pk(e0, e0), pk(e1, e1));
        dXn2[r * 16 + cc1] = make_ulonglong2(pk(e2, e2), pk(e3, e3));
        QXn2[r * 16 + cc0] = make_ulonglong2(pk(sq[0], sq[0]), pk(sq[1], sq[1]));
        QXn2[r * 16 + cc1] = make_ulonglong2(pk(sq[2], sq[2]), pk(sq[3], sq[3]));
    }
}

// Fused hidden layer, K-split across the two thread halves.
// half A (tid<128): i in [0,32);  half B: i in [32,64).
// TWO passes, each SOFTWARE-PIPELINED: loads for iteration t+1 are issued
// before the FMAs consuming iteration t, hiding the LDS latency.
__device__ __forceinline__ void fused_layer(
    float* __restrict__ sm,
    const float* __restrict__ Wy, const float* __restrict__ by,
    const float* __restrict__ Wq, const float* __restrict__ bq,
    const float* __restrict__ X,  const float* __restrict__ dXb,
    const float* __restrict__ QX,
    float* __restrict__ Xn, float* __restrict__ dXn, float* __restrict__ QXn,
    int jg, int pg, int half, int ht)
{
    const ulonglong2* WY2 = (const ulonglong2*)Wy;
    const ulonglong2* WQ2 = (const ulonglong2*)Wq;
    const ulonglong2* X2  = (const ulonglong2*)X;
    const ulonglong2* dX2 = (const ulonglong2*)dXb;
    const ulonglong2* QX2 = (const ulonglong2*)QX;

    const int j0 = jg * 4;
    const int ibase = half * 32;
    const int pg2 = pg * 2;

    u64 ah[2][4], ad[2][4];
    {
        u64 by01 = pk(by[j0], by[j0 + 1]);
        u64 by23 = pk(by[j0 + 2], by[j0 + 3]);
#pragma unroll
        for (int p = 0; p < 4; p++) {
            ah[0][p] = half ? 0ull : by01;
            ah[1][p] = half ? by23 : 0ull;
            ad[0][p] = 0ull; ad[1][p] = 0ull;
        }
    }

    // ---- pass A: h + dh (pipelined) ----
    {
        ulonglong2 wY_c, xa_c, xb_c, da_c, db_c;
        {
            int i = ibase;
            int sw = (i >> 2) & 15;
            int c0 = pg2 ^ sw, c1 = c0 ^ 1;
            wY_c = WY2[i * 16 + jg];
            xa_c = X2[i * 16 + c0];
            xb_c = X2[i * 16 + c1];
            da_c = dX2[i * 16 + c0];
            db_c = dX2[i * 16 + c1];
        }
#pragma unroll
        for (int t = 0; t < 32; t++) {
            ulonglong2 wY_n, xa_n, xb_n, da_n, db_n;
            if (t < 31) {
                int i = ibase + t + 1;
                int sw = (i >> 2) & 15;
                int c0 = pg2 ^ sw, c1 = c0 ^ 1;
                wY_n = WY2[i * 16 + jg];
                xa_n = X2[i * 16 + c0];
                xb_n = X2[i * 16 + c1];
                da_n = dX2[i * 16 + c0];
                db_n = dX2[i * 16 + c1];
            }
            u64 xd[4] = {xa_c.x, xa_c.y, xb_c.x, xb_c.y};
            u64 dd[4] = {da_c.x, da_c.y, db_c.x, db_c.y};
#pragma unroll
            for (int p = 0; p < 4; p++) {
                ah[0][p] = fma2(wY_c.x, xd[p], ah[0][p]);
                ah[1][p] = fma2(wY_c.y, xd[p], ah[1][p]);
                ad[0][p] = fma2(wY_c.x, dd[p], ad[0][p]);
                ad[1][p] = fma2(wY_c.y, dd[p], ad[1][p]);
            }
            if (t < 31) {
                wY_c = wY_n; xa_c = xa_n; xb_c = xb_n; da_c = da_n; db_c = db_n;
            }
        }
    }

    // ---- pass B: q (pipelined) ----
    u64 aq[2][4];
    {
        u64 bq01 = pk(bq[j0], bq[j0 + 1]);
        u64 bq23 = pk(bq[j0 + 2], bq[j0 + 3]);
#pragma unroll
        for (int p = 0; p < 4; p++) {
            aq[0][p] = half ? 0ull : bq01;
            aq[1][p] = half ? bq23 : 0ull;
        }
    }
    {
        ulonglong2 wQ_c, qa_c, qb_c;
        {
            int i = ibase;
            int sw = (i >> 2) & 15;
            int c0 = pg2 ^ sw, c1 = c0 ^ 1;
            wQ_c = WQ2[i * 16 + jg];
            qa_c = QX2[i * 16 + c0];
            qb_c = QX2[i * 16 + c1];
        }
#pragma unroll
        for (int t = 0; t < 32; t++) {
            ulonglong2 wQ_n, qa_n, qb_n;
            if (t < 31) {
                int i = ibase + t + 1;
                int sw = (i >> 2) & 15;
                int c0 = pg2 ^ sw, c1 = c0 ^ 1;
                wQ_n = WQ2[i * 16 + jg];
                qa_n = QX2[i * 16 + c0];
                qb_n = QX2[i * 16 + c1];
            }
            u64 qd[4] = {qa_c.x, qa_c.y, qb_c.x, qb_c.y};
#pragma unroll
            for (int p = 0; p < 4; p++) {
                aq[0][p] = fma2(wQ_c.x, qd[p], aq[0][p]);
                aq[1][p] = fma2(wQ_c.y, qd[p], aq[1][p]);
            }
            if (t < 31) { wQ_c = wQ_n; qa_c = qa_n; qb_c = qb_n; }
        }
    }

    // ---- partial exchange: A gives pair1, B gives pair0 ----
    u64* PX = (u64*)(sm + OFF_PX);   // written by A
    u64* PY = (u64*)(sm + OFF_PY);   // written by B
    if (half == 0) {
#pragma unroll
        for (int p = 0; p < 4; p++) {
            PX[(0 + p) * 128 + ht] = ah[1][p];
            PX[(4 + p) * 128 + ht] = ad[1][p];
            PX[(8 + p) * 128 + ht] = aq[1][p];
        }
    } else {
#pragma unroll
        for (int p = 0; p < 4; p++) {
            PY[(0 + p) * 128 + ht] = ah[0][p];
            PY[(4 + p) * 128 + ht] = ad[0][p];
            PY[(8 + p) * 128 + ht] = aq[0][p];
        }
    }
    __syncthreads();
    if (half == 0) {
#pragma unroll
        for (int p = 0; p < 4; p++) {
            ah[0][p] = add2(ah[0][p], PY[(0 + p) * 128 + ht]);
            ad[0][p] = add2(ad[0][p], PY[(4 + p) * 128 + ht]);
            aq[0][p] = add2(aq[0][p], PY[(8 + p) * 128 + ht]);
        }
        epilogue_rows(Xn, dXn, QXn, j0, pg, ah[0], ad[0], aq[0]);
    } else {
#pragma unroll
        for (int p = 0; p < 4; p++) {
            ah[1][p] = add2(ah[1][p], PX[(0 + p) * 128 + ht]);
            ad[1][p] = add2(ad[1][p], PX[(4 + p) * 128 + ht]);
            aq[1][p] = add2(aq[1][p], PX[(8 + p) * 128 + ht]);
        }
        epilogue_rows(Xn, dXn, QXn, j0 + 2, pg, ah[1], ad[1], aq[1]);
    }
    __syncthreads();
}

// Fused full-net eval; ends with HD written and CTA synced.
__device__ __forceinline__ void eval_fused(float* sm, float tval,
                                           int jg, int pg, int half, int ht,
                                           int tid)
{
    const float* netY = sm;
    const float* netQ = sm + NET_SZ;
    float* X   = sm + OFF_X;
    float* dXb = sm + OFF_DX;
    float* Xn  = sm + OFF_XN;
    float* dXn = sm + OFF_DXN;
    float* QX  = sm + OFF_QX;
    float* QXn = sm + OFF_QXN;
    const float* ys = sm + OFF_YS;

    const int j0 = jg * 4, p0 = pg * 4;

    // ---- input layer ----
    {
        ulonglong2* X2  = (ulonglong2*)X;
        ulonglong2* dX2 = (ulonglong2*)dXb;
        ulonglong2* QX2 = (ulonglong2*)QX;
        float yv[4] = {ys[p0], ys[p0 + 1], ys[p0 + 2], ys[p0 + 3]};
#pragma unroll
        for (int jj = 0; jj < 2; jj++) {
            int r = j0 + half * 2 + jj;
            float wtY = netY[W_IN + r], wyY = netY[W_IN + 64 + r];
            float tbY = fmaf(tval, wtY, netY[B_IN + r]);
            float wtQ = netQ[W_IN + r], wyQ = netQ[W_IN + 64 + r];
            float tbQ = fmaf(tval, wtQ, netQ[B_IN + r]);
            float s[4], c[4], sq[4];
#pragma unroll
            for (int p = 0; p < 4; p++) {
                __sincosf(fmaf(yv[p], wyY, tbY), &s[p], &c[p]);
                sq[p] = __sinf(fmaf(yv[p], wyQ, tbQ));
            }
            int cc0 = swz(pg * 2, r);
            int cc1 = swz(pg * 2 + 1, r);
            X2[r * 16 + cc0] = make_ulonglong2(pk(s[0], s[0]), pk(s[1], s[1]));
            X2[r * 16 + cc1] = make_ulonglong2(pk(s[2], s[2]), pk(s[3], s[3]));
            float d0 = c[0] * wyY, d1 = c[1] * wyY, d2 = c[2] * wyY, d3 = c[3] * wyY;
            dX2[r * 16 + cc0] = make_ulonglong2(pk(d0, d0), pk(d1, d1));
            dX2[r * 16 + cc1] = make_ulonglong2(pk(d2, d2), pk(d3, d3));
            QX2[r * 16 + cc0] = make_ulonglong2(pk(sq[0], sq[0]), pk(sq[1], sq[1]));
            QX2[r * 16 + cc1] = make_ulonglong2(pk(sq[2], sq[2]), pk(sq[3], sq[3]));
        }
    }
    __syncthreads();
    fused_layer(sm, netY + W_H,        netY + B_H,       netQ + W_H,        netQ + B_H,
                X, dXb, QX, Xn, dXn, QXn, jg, pg, half, ht);
    fused_layer(sm, netY + W_H + 4096, netY + B_H + 64,  netQ + W_H + 4096, netQ + B_H + 64,
                Xn, dXn, QXn, X, dXb, QX, jg, pg, half, ht);
    fused_layer(sm, netY + W_H + 8192, netY + B_H + 128, netQ + W_H + 8192, netQ + B_H + 128,
                X, dXb, QX, Xn, dXn, QXn, jg, pg, half, ht);

    // ---- output heads, i-split: A warps 0-2 do i<32, B warps 4-6 do i>=32 ----
    const int wid = tid >> 5, lane = tid & 31;
    float* HD2 = sm + OFF_HD2;
    float* HD  = sm + OFF_HD;
    int hw = wid & 3;
    if (hw < 3) {
        const float* src = (hw == 0) ? Xn : (hw == 1) ? dXn : QXn;
        const float* wv  = (hw == 2) ? (netQ + W_OUT) : (netY + W_OUT);
        int i0 = half * 32;
        float a0 = 0.0f, a1 = 0.0f, a2 = 0.0f, a3 = 0.0f;
        int p = lane;
#pragma unroll 4
        for (int i = 0; i < 32; i += 4) {
#pragma unroll
            for (int k = 0; k < 4; k++) {
                int ii = i0 + i + k;
                int ch = swz(p >> 1, ii);
                int off = ii * 64 + ch * 4 + (p & 1) * 2;
                float v = src[off] * wv[ii];
                if (k == 0) a0 += v; else if (k == 1) a1 += v;
                else if (k == 2) a2 += v; else a3 += v;
            }
        }
        HD2[half * 96 + hw * 32 + lane] = (a0 + a1) + (a2 + a3);
    }
    __syncthreads();
    if (tid < 96) {
        int head = tid >> 5;
        float bias = (head == 0) ? netY[B_OUT] : (head == 2) ? netQ[B_OUT] : 0.0f;
        HD[tid] = HD2[tid] + HD2[96 + tid] + bias;
    }
    __syncthreads();
}

__global__ __launch_bounds__(NTHR, 1) void fbsnn_main(
    const float* __restrict__ yWin,  const float* __restrict__ yBin,
    const float* __restrict__ yWh,   const float* __restrict__ yBh,
    const float* __restrict__ yWout, const float* __restrict__ yBout,
    const float* __restrict__ qWin,  const float* __restrict__ qBin,
    const float* __restrict__ qWh,   const float* __restrict__ qBh,
    const float* __restrict__ qWout, const float* __restrict__ qBout,
    const float* __restrict__ y0,    const float* __restrict__ dW,
    float* __restrict__ out)
{
    extern __shared__ float sm[];
    const int tid = threadIdx.x;
    const int half = tid >> 7;
    const int ht = tid & 127;
    const int jg = ht & 15;
    const int pg = ht >> 4;

    // ---- stage all weights into smem once ----
    cpf(sm + W_IN,  yWin, 128,   tid);
    cpf(sm + B_IN,  yBin, 64,    tid);
    cpf(sm + W_H,   yWh,  12288, tid);
    cpf(sm + B_H,   yBh,  192,   tid);
    cpf(sm + W_OUT, yWout, 64,   tid);
    if (tid == 0) sm[B_OUT] = yBout[0];
    float* smq = sm + NET_SZ;
    cpf(smq + W_IN,  qWin, 128,   tid);
    cpf(smq + B_IN,  qBin, 64,    tid);
    cpf(smq + W_H,   qWh,  12288, tid);
    cpf(smq + B_H,   qBh,  192,   tid);
    cpf(smq + W_OUT, qWout, 64,   tid);
    if (tid == 0) smq[B_OUT] = qBout[0];
    if (tid < 32) sm[OFF_YS + tid] = y0[0];
    __syncthreads();

    float lossAcc = 0.0f, Ytilde = 0.0f;
    const int pbase = blockIdx.x * PPC;
    float* HD = sm + OFF_HD;

    // initial fused eval at t = 0: gives Y0, dY0, q0
    eval_fused(sm, 0.0f, jg, pg, half, ht, tid);

    for (int n = 0; n < NSTEP; n++) {
        if (tid < 32) {
            float Yc  = HD[tid];
            float dYv = HD[32 + tid];
            float qv  = HD[64 + tid];
            float dwn = SQRT_DT * dW[n * BATCH + pbase + tid];
            Ytilde = Yc - qv * qv * DTV + SIGMA * dYv * dwn;
            sm[OFF_YS + tid] += qv * DTV + SIGMA * dwn;
        }
        __syncthreads();

        eval_fused(sm, (float)(n + 1) * DTV, jg, pg, half, ht, tid);

        if (tid < 32) {
            float e = HD[tid] - Ytilde;
            lossAcc = fmaf(e, e, lossAcc);
        }
    }

    if (tid < 32) {
        float yN = sm[OFF_YS + tid];
        float e1 = HD[tid]      - yN * yN;   // terminal value residual
        float e2 = HD[32 + tid] - 2.0f * yN; // terminal gradient residual
        lossAcc = fmaf(e1, e1, fmaf(e2, e2, lossAcc));
#pragma unroll
        for (int o = 16; o > 0; o >>= 1)
            lossAcc += __shfl_down_sync(0xffffffffu, lossAcc, o);
        if (tid == 0) g_part[blockIdx.x] = lossAcc;
    }

    // ---- last-CTA deterministic reduction (single-launch design) ----
    if (tid == 0) {
        __threadfence();
        int old = atomicAdd(&g_count, 1);
        if (old == NCTA - 1) {
            __threadfence();
            float acc = 0.0f;
#pragma unroll 8
            for (int i = 0; i < NCTA; i++) acc += g_part[i];
            out[0] = acc * (1.0f / (float)BATCH);
            g_count = 0;
        }
    }
}

extern "C" void kernel_launch(void* const* d_in, const int* in_sizes, int n_in,
                              void* d_out, int out_size)
{
    const float *yWin, *yBin, *yWh, *yBh, *yWout, *yBout;
    const float *qWin, *qBin, *qWh, *qBh, *qWout, *qBout;
    const float *y0, *dW;

    if (in_sizes[0] == 1) {
        y0    = (const float*)d_in[0];
        yWin  = (const float*)d_in[1];
        yBin  = (const float*)d_in[2];
        yWh   = (const float*)d_in[3];
        yBh   = (const float*)d_in[4];
        yWout = (const float*)d_in[5];
        yBout = (const float*)d_in[6];
        qWin  = (const float*)d_in[7];
        qBin  = (const float*)d_in[8];
        qWh   = (const float*)d_in[9];
        qBh   = (const float*)d_in[10];
        qWout = (const float*)d_in[11];
        qBout = (const float*)d_in[12];
        dW    = (const float*)d_in[13];
    } else {
        yWin  = (const float*)d_in[0];
        yBin  = (const float*)d_in[1];
        yWh   = (const float*)d_in[2];
        yBh   = (const float*)d_in[3];
        yWout = (const float*)d_in[4];
        yBout = (const float*)d_in[5];
        qWin  = (const float*)d_in[6];
        qBin  = (const float*)d_in[7];
        qWh   = (const float*)d_in[8];
        qBh   = (const float*)d_in[9];
        qWout = (const float*)d_in[10];
        qBout = (const float*)d_in[11];
        y0    = (const float*)d_in[12];
        dW    = (const float*)d_in[13];
    }

    cudaFuncSetAttribute(fbsnn_main, cudaFuncAttributeMaxDynamicSharedMemorySize,
                         SMEM_BYTES);

    fbsnn_main<<<NCTA, NTHR, SMEM_BYTES>>>(yWin, yBin, yWh, yBh, yWout, yBout,
                                           qWin, qBin, qWh, qBh, qWout, qBout,
                                           y0, dW, (float*)d_out);
}

// round 14
// speedup vs baseline: 1.9009x; 1.0160x over previous
#include <cuda_runtime.h>

#define DTV      0.02f
#define SQRT_DT  0.141421356237309515f
#define SIGMA    0.5f
#define NSTEP    50
#define BATCH    4096
#define PPC      32            // paths per CTA
#define NCTA     (BATCH / PPC) // 128
#define NTHR     384           // 8 Y-warps + 4 q-warps

typedef unsigned long long u64;

// ---- shared-memory layout (float offsets) ----
#define W_IN   0       // [2][64] = 128
#define B_IN   128     // 64
#define W_H    192     // [3][64][64] = 12288
#define B_H    12480   // [3][64] = 192
#define W_OUT  12672   // 64
#define B_OUT  12736   // 1 (+3 pad)
#define NET_SZ 12740
// activations: plain [64 rows][32 paths] floats, 128B rows, NO swizzle
#define ABUF     2048
#define OFF_X0   (2 * NET_SZ)          // 25480
#define OFF_DX0  (OFF_X0  + ABUF)
#define OFF_X1   (OFF_DX0 + ABUF)
#define OFF_DX1  (OFF_X1  + ABUF)
#define OFF_QX0  (OFF_DX1 + ABUF)
#define OFF_QX1  (OFF_QX0 + ABUF)
#define OFF_YS   (OFF_QX1 + ABUF)
#define OFF_HD2  (OFF_YS  + 32)        // [Y:2x32 | dY:2x32 | q:2x32] = 192
#define SMEM_FLOATS (OFF_HD2 + 192)
#define SMEM_BYTES  (SMEM_FLOATS * 4)  // ~152 KB

#define BARY() asm volatile("bar.sync 1, 256;" ::: "memory")
#define BARQ() asm volatile("bar.sync 2, 128;" ::: "memory")

__device__ float g_part[NCTA];
__device__ int   g_count = 0;

__device__ __forceinline__ void cpf(float* d, const float* s, int n, int tid) {
    for (int i = tid; i < n; i += NTHR) d[i] = s[i];
}

__device__ __forceinline__ u64 fma2(u64 a, u64 b, u64 c) {
    u64 d;
    asm("fma.rn.f32x2 %0, %1, %2, %3;" : "=l"(d) : "l"(a), "l"(b), "l"(c));
    return d;
}
__device__ __forceinline__ u64 pk(float lo, float hi) {
    u64 r;
    asm("mov.b64 %0, {%1, %2};" : "=l"(r) : "f"(lo), "f"(hi));
    return r;
}
__device__ __forceinline__ void upk(u64 v, float& lo, float& hi) {
    asm("mov.b64 {%0, %1}, %2;" : "=f"(lo), "=f"(hi) : "l"(v));
}

// ---- team Y hidden layer: h + dh for rows j0, j0+1, paths p0..p0+3 ----
__device__ __forceinline__ void layerY(
    const float* __restrict__ Wy, const float* __restrict__ by,
    const float* __restrict__ X,  const float* __restrict__ DX,
    float* __restrict__ Xn, float* __restrict__ DXn,
    int j0, int p0)
{
    const float2* W2 = (const float2*)Wy;   // 32 float2 per 64-float row
    const int wj = j0 >> 1;

    u64 h0a = pk(by[j0], by[j0]),       h0b = h0a;
    u64 h1a = pk(by[j0 + 1], by[j0 + 1]), h1b = h1a;
    u64 d0a = 0ull, d0b = 0ull, d1a = 0ull, d1b = 0ull;

#pragma unroll 8
    for (int i = 0; i < 64; i++) {
        float2 w = W2[i * 32 + wj];
        ulonglong2 xv = *(const ulonglong2*)(X  + i * 32 + p0);
        ulonglong2 dv = *(const ulonglong2*)(DX + i * 32 + p0);
        u64 w0 = pk(w.x, w.x);
        u64 w1 = pk(w.y, w.y);
        h0a = fma2(w0, xv.x, h0a); h0b = fma2(w0, xv.y, h0b);
        h1a = fma2(w1, xv.x, h1a); h1b = fma2(w1, xv.y, h1b);
        d0a = fma2(w0, dv.x, d0a); d0b = fma2(w0, dv.y, d0b);
        d1a = fma2(w1, dv.x, d1a); d1b = fma2(w1, dv.y, d1b);
    }

    float h[2][4], d[2][4];
    upk(h0a, h[0][0], h[0][1]); upk(h0b, h[0][2], h[0][3]);
    upk(h1a, h[1][0], h[1][1]); upk(h1b, h[1][2], h[1][3]);
    upk(d0a, d[0][0], d[0][1]); upk(d0b, d[0][2], d[0][3]);
    upk(d1a, d[1][0], d[1][1]); upk(d1b, d[1][2], d[1][3]);
#pragma unroll
    for (int rr = 0; rr < 2; rr++) {
        float s[4], c[4];
#pragma unroll
        for (int p = 0; p < 4; p++) __sincosf(h[rr][p], &s[p], &c[p]);
        *(float4*)(Xn  + (j0 + rr) * 32 + p0) = make_float4(s[0], s[1], s[2], s[3]);
        *(float4*)(DXn + (j0 + rr) * 32 + p0) =
            make_float4(c[0] * d[rr][0], c[1] * d[rr][1],
                        c[2] * d[rr][2], c[3] * d[rr][3]);
    }
}

// ---- team Q hidden layer: q for rows j0..j0+3, paths p0..p0+3 ----
__device__ __forceinline__ void layerQ(
    const float* __restrict__ Wq, const float* __restrict__ bq,
    const float* __restrict__ QX, float* __restrict__ QXn,
    int j0, int p0)
{
    u64 a0a = pk(bq[j0], bq[j0]),         a0b = a0a;
    u64 a1a = pk(bq[j0 + 1], bq[j0 + 1]), a1b = a1a;
    u64 a2a = pk(bq[j0 + 2], bq[j0 + 2]), a2b = a2a;
    u64 a3a = pk(bq[j0 + 3], bq[j0 + 3]), a3b = a3a;

#pragma unroll 8
    for (int i = 0; i < 64; i++) {
        float4 w = *(const float4*)(Wq + i * 64 + j0);
        ulonglong2 qv = *(const ulonglong2*)(QX + i * 32 + p0);
        u64 w0 = pk(w.x, w.x), w1 = pk(w.y, w.y);
        u64 w2 = pk(w.z, w.z), w3 = pk(w.w, w.w);
        a0a = fma2(w0, qv.x, a0a); a0b = fma2(w0, qv.y, a0b);
        a1a = fma2(w1, qv.x, a1a); a1b = fma2(w1, qv.y, a1b);
        a2a = fma2(w2, qv.x, a2a); a2b = fma2(w2, qv.y, a2b);
        a3a = fma2(w3, qv.x, a3a); a3b = fma2(w3, qv.y, a3b);
    }

    u64 aa[4] = {a0a, a1a, a2a, a3a};
    u64 ab[4] = {a0b, a1b, a2b, a3b};
#pragma unroll
    for (int rr = 0; rr < 4; rr++) {
        float v[4];
        upk(aa[rr], v[0], v[1]);
        upk(ab[rr], v[2], v[3]);
#pragma unroll
        for (int p = 0; p < 4; p++) v[p] = __sinf(v[p]);
        *(float4*)(QXn + (j0 + rr) * 32 + p0) = make_float4(v[0], v[1], v[2], v[3]);
    }
}

// Full fused eval: teams run independently, rendezvous at final syncthreads.
// Results: HD2 = [Y ih0|Y ih1 | dY ih0|dY ih1 | q ih0|q ih1] partials.
__device__ __forceinline__ void eval_all(float* sm, float tval,
                                         int tid, int wid, int lane)
{
    const float* netY = sm;
    const float* netQ = sm + NET_SZ;
    float* X0  = sm + OFF_X0;
    float* DX0 = sm + OFF_DX0;
    float* X1  = sm + OFF_X1;
    float* DX1 = sm + OFF_DX1;
    float* QX0 = sm + OFF_QX0;
    float* QX1 = sm + OFF_QX1;
    const float* ys = sm + OFF_YS;
    float* HD2 = sm + OFF_HD2;

    if (tid < 256) {
        // ================= team Y =================
        // input layer: 512 (row, chunk) tasks over 256 threads
#pragma unroll
        for (int k = 0; k < 2; k++) {
            int u = tid + k * 256;
            int r = u >> 3, ch = u & 7, p0 = ch * 4;
            float wt = netY[W_IN + r], wy = netY[W_IN + 64 + r];
            float tb = fmaf(tval, wt, netY[B_IN + r]);
            float s[4], c[4];
#pragma unroll
            for (int p = 0; p < 4; p++)
                __sincosf(fmaf(ys[p0 + p], wy, tb), &s[p], &c[p]);
            *(float4*)(X0 + r * 32 + p0) = make_float4(s[0], s[1], s[2], s[3]);
            *(float4*)(DX0 + r * 32 + p0) =
                make_float4(c[0] * wy, c[1] * wy, c[2] * wy, c[3] * wy);
        }
        BARY();

        const int jsub = lane >> 3, psub = lane & 7;
        const int j0 = wid * 8 + jsub * 2;
        const int p0 = psub * 4;
        layerY(netY + W_H,        netY + B_H,       X0, DX0, X1, DX1, j0, p0);
        BARY();
        layerY(netY + W_H + 4096, netY + B_H + 64,  X1, DX1, X0, DX0, j0, p0);
        BARY();
        layerY(netY + W_H + 8192, netY + B_H + 128, X0, DX0, X1, DX1, j0, p0);
        BARY();

        // heads: warps 0-3 = (head: Y/dY) x (i-half)
        if (wid < 4) {
            int head = wid >> 1, ih = wid & 1;
            const float* src = head ? DX1 : X1;
            const float* wv  = netY + W_OUT;
            int i0 = ih * 32;
            float a0 = 0.0f, a1 = 0.0f;
#pragma unroll 8
            for (int i = 0; i < 32; i += 2) {
                a0 = fmaf(src[(i0 + i) * 32 + lane],     wv[i0 + i],     a0);
                a1 = fmaf(src[(i0 + i + 1) * 32 + lane], wv[i0 + i + 1], a1);
            }
            HD2[head * 64 + ih * 32 + lane] = a0 + a1;
        }
    } else {
        // ================= team Q =================
        const int qt = tid - 256;              // 0..127
#pragma unroll
        for (int k = 0; k < 4; k++) {
            int u = qt + k * 128;
            int r = u >> 3, ch = u & 7, p0 = ch * 4;
            float wt = netQ[W_IN + r], wy = netQ[W_IN + 64 + r];
            float tb = fmaf(tval, wt, netQ[B_IN + r]);
            float sq[4];
#pragma unroll
            for (int p = 0; p < 4; p++)
                sq[p] = __sinf(fmaf(ys[p0 + p], wy, tb));
            *(float4*)(QX0 + r * 32 + p0) = make_float4(sq[0], sq[1], sq[2], sq[3]);
        }
        BARQ();

        const int qw = wid - 8;                // 0..3
        const int jsub = lane >> 3, psub = lane & 7;
        const int j0 = qw * 16 + jsub * 4;
        const int p0 = psub * 4;
        layerQ(netQ + W_H,        netQ + B_H,       QX0, QX1, j0, p0);
        BARQ();
        layerQ(netQ + W_H + 4096, netQ + B_H + 64,  QX1, QX0, j0, p0);
        BARQ();
        layerQ(netQ + W_H + 8192, netQ + B_H + 128, QX0, QX1, j0, p0);
        BARQ();

        // q head: warps 8,9 = i-halves
        if (wid < 10) {
            int ih = wid & 1;
            const float* wv = netQ + W_OUT;
            int i0 = ih * 32;
            float a0 = 0.0f, a1 = 0.0f;
#pragma unroll 8
            for (int i = 0; i < 32; i += 2) {
                a0 = fmaf(QX1[(i0 + i) * 32 + lane],     wv[i0 + i],     a0);
                a1 = fmaf(QX1[(i0 + i + 1) * 32 + lane], wv[i0 + i + 1], a1);
            }
            HD2[128 + ih * 32 + lane] = a0 + a1;
        }
    }
    __syncthreads();
}

__global__ __launch_bounds__(NTHR, 1) void fbsnn_main(
    const float* __restrict__ yWin,  const float* __restrict__ yBin,
    const float* __restrict__ yWh,   const float* __restrict__ yBh,
    const float* __restrict__ yWout, const float* __restrict__ yBout,
    const float* __restrict__ qWin,  const float* __restrict__ qBin,
    const float* __restrict__ qWh,   const float* __restrict__ qBh,
    const float* __restrict__ qWout, const float* __restrict__ qBout,
    const float* __restrict__ y0,    const float* __restrict__ dW,
    float* __restrict__ out)
{
    extern __shared__ float sm[];
    const int tid  = threadIdx.x;
    const int wid  = tid >> 5;
    const int lane = tid & 31;

    // ---- stage all weights into smem once ----
    cpf(sm + W_IN,  yWin, 128,   tid);
    cpf(sm + B_IN,  yBin, 64,    tid);
    cpf(sm + W_H,   yWh,  12288, tid);
    cpf(sm + B_H,   yBh,  192,   tid);
    cpf(sm + W_OUT, yWout, 64,   tid);
    if (tid == 0) sm[B_OUT] = yBout[0];
    float* smq = sm + NET_SZ;
    cpf(smq + W_IN,  qWin, 128,   tid);
    cpf(smq + B_IN,  qBin, 64,    tid);
    cpf(smq + W_H,   qWh,  12288, tid);
    cpf(smq + B_H,   qBh,  192,   tid);
    cpf(smq + W_OUT, qWout, 64,   tid);
    if (tid == 0) smq[B_OUT] = qBout[0];
    if (tid < 32) sm[OFF_YS + tid] = y0[0];
    __syncthreads();

    const int pbase = blockIdx.x * PPC;
    const float* HD2 = sm + OFF_HD2;

    float lossAcc = 0.0f, Ytilde = 0.0f;
    float dwcur = 0.0f;
    if (wid == 0) dwcur = dW[pbase + lane];   // prefetch step 0

    // initial eval at t = 0
    eval_all(sm, 0.0f, tid, wid, lane);

    for (int n = 0; n < NSTEP; n++) {
        if (wid == 0) {
            int p = lane;
            float Yv  = HD2[p]      + HD2[32 + p]  + sm[B_OUT];
            float dYv = HD2[64 + p] + HD2[96 + p];
            float qv  = HD2[128 + p] + HD2[160 + p] + sm[NET_SZ + B_OUT];
            if (n > 0) {
                float e = Yv - Ytilde;
                lossAcc = fmaf(e, e, lossAcc);
            }
            float dwn = SQRT_DT * dwcur;
            Ytilde = Yv - qv * qv * DTV + SIGMA * dYv * dwn;
            sm[OFF_YS + p] += qv * DTV + SIGMA * dwn;
            if (n + 1 < NSTEP) dwcur = dW[(n + 1) * BATCH + pbase + p];
        }
        __syncthreads();

        eval_all(sm, (float)(n + 1) * DTV, tid, wid, lane);
    }

    if (wid == 0) {
        int p = lane;
        float Yv  = HD2[p]      + HD2[32 + p]  + sm[B_OUT];
        float dYv = HD2[64 + p] + HD2[96 + p];
        float e = Yv - Ytilde;
        lossAcc = fmaf(e, e, lossAcc);
        float yN = sm[OFF_YS + p];
        float e1 = Yv - yN * yN;
        float e2 = dYv - 2.0f * yN;
        lossAcc = fmaf(e1, e1, fmaf(e2, e2, lossAcc));
#pragma unroll
        for (int o = 16; o > 0; o >>= 1)
            lossAcc += __shfl_down_sync(0xffffffffu, lossAcc, o);
        if (lane == 0) g_part[blockIdx.x] = lossAcc;
    }

    // ---- last-CTA deterministic reduction (single launch) ----
    if (tid == 0) {
        __threadfence();
        int old = atomicAdd(&g_count, 1);
        if (old == NCTA - 1) {
            __threadfence();
            float acc = 0.0f;
#pragma unroll 8
            for (int i = 0; i < NCTA; i++) acc += g_part[i];
            out[0] = acc * (1.0f / (float)BATCH);
            g_count = 0;
        }
    }
}

extern "C" void kernel_launch(void* const* d_in, const int* in_sizes, int n_in,
                              void* d_out, int out_size)
{
    const float *yWin, *yBin, *yWh, *yBh, *yWout, *yBout;
    const float *qWin, *qBin, *qWh, *qBh, *qWout, *qBout;
    const float *y0, *dW;

    if (in_sizes[0] == 1) {
        y0    = (const float*)d_in[0];
        yWin  = (const float*)d_in[1];
        yBin  = (const float*)d_in[2];
        yWh   = (const float*)d_in[3];
        yBh   = (const float*)d_in[4];
        yWout = (const float*)d_in[5];
        yBout = (const float*)d_in[6];
        qWin  = (const float*)d_in[7];
        qBin  = (const float*)d_in[8];
        qWh   = (const float*)d_in[9];
        qBh   = (const float*)d_in[10];
        qWout = (const float*)d_in[11];
        qBout = (const float*)d_in[12];
        dW    = (const float*)d_in[13];
    } else {
        yWin  = (const float*)d_in[0];
        yBin  = (const float*)d_in[1];
        yWh   = (const float*)d_in[2];
        yBh   = (const float*)d_in[3];
        yWout = (const float*)d_in[4];
        yBout = (const float*)d_in[5];
        qWin  = (const float*)d_in[6];
        qBin  = (const float*)d_in[7];
        qWh   = (const float*)d_in[8];
        qBh   = (const float*)d_in[9];
        qWout = (const float*)d_in[10];
        qBout = (const float*)d_in[11];
        y0    = (const float*)d_in[12];
        dW    = (const float*)d_in[13];
    }

    cudaFuncSetAttribute(fbsnn_main, cudaFuncAttributeMaxDynamicSharedMemorySize,
                         SMEM_BYTES);

    fbsnn_main<<<NCTA, NTHR, SMEM_BYTES>>>(yWin, yBin, yWh, yBh, yWout, yBout,
                                           qWin, qBin, qWh, qBh, qWout, qBout,
                                           y0, dW, (float*)d_out);
}